// round 1
// baseline (speedup 1.0000x reference)
#include <cuda_runtime.h>
#include <cstdint>

#define N_NODES 100000
#define N_EDGES 1600000
#define R 4
#define NG 256
#define MAXDIN 32

// ---- scratch (device globals; no allocation allowed) ----
__device__ int      g_cnt[N_NODES * R];            // per (node, relation) in-degree
__device__ float    g_acc[N_NODES * R * MAXDIN];   // per (node, relation) feature sums
__device__ float    g_h1[N_NODES * 16];
__device__ float    g_h2[N_NODES * 32];
__device__ float    g_h3[N_NODES * 64];
__device__ unsigned g_pool[NG * 64];               // order-encoded float max

// encode float -> unsigned s.t. unsigned order == float order
__device__ __forceinline__ unsigned enc(float v) {
    unsigned u = __float_as_uint(v);
    return (u & 0x80000000u) ? ~u : (u | 0x80000000u);
}
__device__ __forceinline__ float dec(unsigned u) {
    unsigned bits = (u & 0x80000000u) ? (u ^ 0x80000000u) : ~u;
    return __uint_as_float(bits);
}

// ---- init: zero counts, set pool to encode(-inf) ----
__global__ void init_kernel() {
    int i = blockIdx.x * blockDim.x + threadIdx.x;
    if (i < N_NODES * R) g_cnt[i] = 0;
    if (i < NG * 64)     g_pool[i] = 0x007FFFFFu;   // enc(-inf)
}

// ---- count edges per (dst, relation) ----
__global__ void count_kernel(const int* __restrict__ dst,
                             const int* __restrict__ et) {
    int e = blockIdx.x * blockDim.x + threadIdx.x;
    if (e < N_EDGES) atomicAdd(&g_cnt[dst[e] * R + et[e]], 1);
}

// ---- zero the active portion of g_acc (vectorized) ----
__global__ void zero_acc_kernel(int n4) {
    int i = blockIdx.x * blockDim.x + threadIdx.x;
    if (i < n4) reinterpret_cast<float4*>(g_acc)[i] = make_float4(0.f, 0.f, 0.f, 0.f);
}

// ---- scatter: acc[(dst,rel), :] += x[src, :] ----
template <int DIN>
__global__ void scatter_kernel(const float* __restrict__ xin,
                               const int* __restrict__ src,
                               const int* __restrict__ dst,
                               const int* __restrict__ et) {
    unsigned idx = blockIdx.x * blockDim.x + threadIdx.x;
    if (idx >= (unsigned)N_EDGES * DIN) return;
    unsigned e = idx / DIN;
    unsigned d = idx % DIN;
    int s  = src[e];
    int dd = dst[e];
    int r  = et[e];
    atomicAdd(&g_acc[(dd * R + r) * DIN + d], xin[s * DIN + d]);
}

// ---- dense per-node transform: out = sum_r (acc/cnt) @ W[r] + x @ root + b ----
template <int DIN, int DOUT, bool RELU>
__global__ void transform_kernel(const float* __restrict__ xin,
                                 const float* __restrict__ W,     // [R, DIN, DOUT]
                                 const float* __restrict__ root,  // [DIN, DOUT]
                                 const float* __restrict__ bias,  // [DOUT]
                                 float* __restrict__ hout) {
    constexpr int WSZ = R * DIN * DOUT;
    constexpr int TOT = WSZ + DIN * DOUT;
    __shared__ float sW[TOT + DOUT];
    for (int i = threadIdx.x; i < WSZ; i += blockDim.x)       sW[i] = W[i];
    for (int i = threadIdx.x; i < DIN * DOUT; i += blockDim.x) sW[WSZ + i] = root[i];
    for (int i = threadIdx.x; i < DOUT; i += blockDim.x)      sW[TOT + i] = bias[i];
    __syncthreads();

    constexpr int NPB = 256 / DOUT;
    int n = blockIdx.x * NPB + threadIdx.x / DOUT;
    int o = threadIdx.x % DOUT;
    if (n >= N_NODES) return;

    float sum = sW[TOT + o];
    const float* xr = xin + n * DIN;
#pragma unroll
    for (int i = 0; i < DIN; i++)
        sum += xr[i] * sW[WSZ + i * DOUT + o];

#pragma unroll
    for (int r = 0; r < R; r++) {
        float inv = 1.0f / fmaxf((float)g_cnt[n * R + r], 1.0f);
        const float* ar = g_acc + (n * R + r) * DIN;
        const float* wr = sW + r * DIN * DOUT;
#pragma unroll
        for (int i = 0; i < DIN; i++)
            sum += (ar[i] * inv) * wr[i * DOUT + o];
    }
    hout[n * DOUT + o] = RELU ? fmaxf(sum, 0.0f) : sum;
}

// ---- segment-max pooling over graphs ----
__global__ void pool_kernel(const int* __restrict__ batch) {
    unsigned idx = blockIdx.x * blockDim.x + threadIdx.x;
    if (idx >= (unsigned)N_NODES * 64u) return;
    unsigned n = idx >> 6;
    unsigned c = idx & 63u;
    float v = g_h3[idx];
    atomicMax(&g_pool[batch[n] * 64 + c], enc(v));
}

__global__ void decode_kernel(float* __restrict__ out) {
    int i = blockIdx.x * blockDim.x + threadIdx.x;
    if (i < NG * 64) out[i] = dec(g_pool[i]);
}

extern "C" void kernel_launch(void* const* d_in, const int* in_sizes, int n_in,
                              void* d_out, int out_size) {
    const float* x     = (const float*)d_in[0];
    const int*   ei    = (const int*)d_in[1];
    const int*   src   = ei;
    const int*   dst   = ei + N_EDGES;
    const int*   et    = (const int*)d_in[2];
    const int*   batch = (const int*)d_in[3];
    const float* W1 = (const float*)d_in[4];
    const float* r1 = (const float*)d_in[5];
    const float* b1 = (const float*)d_in[6];
    const float* W2 = (const float*)d_in[7];
    const float* r2 = (const float*)d_in[8];
    const float* b2 = (const float*)d_in[9];
    const float* W3 = (const float*)d_in[10];
    const float* r3 = (const float*)d_in[11];
    const float* b3 = (const float*)d_in[12];
    float* out = (float*)d_out;

    float *h1p, *h2p, *h3p;
    cudaGetSymbolAddress((void**)&h1p, g_h1);
    cudaGetSymbolAddress((void**)&h2p, g_h2);
    cudaGetSymbolAddress((void**)&h3p, g_h3);

    const int T = 256;

    // structure (once per launch, shared by all layers)
    init_kernel<<<(N_NODES * R + T - 1) / T, T>>>();
    count_kernel<<<(N_EDGES + T - 1) / T, T>>>(dst, et);

    // ---- layer 1: 16 -> 16, relu ----
    {
        int n4 = N_NODES * R * 16 / 4;
        zero_acc_kernel<<<(n4 + T - 1) / T, T>>>(n4);
        scatter_kernel<16><<<((unsigned)N_EDGES * 16 + T - 1) / T, T>>>(x, src, dst, et);
        transform_kernel<16, 16, true><<<(N_NODES + 15) / 16, T>>>(x, W1, r1, b1, h1p);
    }
    // ---- layer 2: 16 -> 32, relu ----
    {
        int n4 = N_NODES * R * 16 / 4;
        zero_acc_kernel<<<(n4 + T - 1) / T, T>>>(n4);
        scatter_kernel<16><<<((unsigned)N_EDGES * 16 + T - 1) / T, T>>>(h1p, src, dst, et);
        transform_kernel<16, 32, true><<<(N_NODES + 7) / 8, T>>>(h1p, W2, r2, b2, h2p);
    }
    // ---- layer 3: 32 -> 64, no relu ----
    {
        int n4 = N_NODES * R * 32 / 4;
        zero_acc_kernel<<<(n4 + T - 1) / T, T>>>(n4);
        scatter_kernel<32><<<((unsigned)N_EDGES * 32 + T - 1) / T, T>>>(h2p, src, dst, et);
        transform_kernel<32, 64, false><<<(N_NODES + 3) / 4, T>>>(h2p, W3, r3, b3, h3p);
    }

    // ---- max pooling ----
    pool_kernel<<<((unsigned)N_NODES * 64 + T - 1) / T, T>>>(batch);
    decode_kernel<<<(NG * 64 + T - 1) / T, T>>>(out);
}

// round 2
// speedup vs baseline: 2.1955x; 2.1955x over previous
#include <cuda_runtime.h>

#define N_NODES 100000
#define N_EDGES 1600000
#define R 4
#define NG 256
#define SEG (N_NODES * R)              // 400000
#define SCAN_B 1024
#define NBLK ((SEG + SCAN_B - 1) / SCAN_B)   // 391

// ---- scratch (device globals; no allocation allowed) ----
__device__ int      g_cnt[SEG];
__device__ int      g_off[SEG];
__device__ int      g_fill[SEG];
__device__ int      g_partial[NBLK];
__device__ int      g_esrc[N_EDGES];
__device__ float    g_h1[N_NODES * 16];
__device__ float    g_h2[N_NODES * 32];
__device__ float    g_h3[N_NODES * 64];
__device__ unsigned g_pool[NG * 64];

// order-preserving float<->unsigned encoding for atomicMax
__device__ __forceinline__ unsigned enc(float v) {
    unsigned u = __float_as_uint(v);
    return (u & 0x80000000u) ? ~u : (u | 0x80000000u);
}
__device__ __forceinline__ float dec(unsigned u) {
    unsigned bits = (u & 0x80000000u) ? (u ^ 0x80000000u) : ~u;
    return __uint_as_float(bits);
}

// ---- init: zero counts + fill counters, pool = enc(-inf) ----
__global__ void init_kernel() {
    int i = blockIdx.x * blockDim.x + threadIdx.x;
    if (i < SEG) { g_cnt[i] = 0; g_fill[i] = 0; }
    if (i < NG * 64) g_pool[i] = 0x007FFFFFu;   // enc(-inf)
}

// ---- count edges per (dst, relation) ----
__global__ void count_kernel(const int* __restrict__ dst,
                             const int* __restrict__ et) {
    int e = blockIdx.x * blockDim.x + threadIdx.x;
    if (e < N_EDGES) atomicAdd(&g_cnt[dst[e] * R + et[e]], 1);
}

// ---- exclusive prefix scan over g_cnt -> g_off (3-phase) ----
__global__ void scan1_kernel() {
    __shared__ int s[SCAN_B];
    int i = blockIdx.x * SCAN_B + threadIdx.x;
    int v = (i < SEG) ? g_cnt[i] : 0;
    s[threadIdx.x] = v;
    __syncthreads();
    for (int d = 1; d < SCAN_B; d <<= 1) {
        int t = (threadIdx.x >= d) ? s[threadIdx.x - d] : 0;
        __syncthreads();
        s[threadIdx.x] += t;
        __syncthreads();
    }
    if (i < SEG) g_off[i] = s[threadIdx.x] - v;          // exclusive within block
    if (threadIdx.x == SCAN_B - 1) g_partial[blockIdx.x] = s[threadIdx.x];
}

__global__ void scan2_kernel() {   // single block of 512 scans the 391 partials
    __shared__ int s[512];
    int v = (threadIdx.x < NBLK) ? g_partial[threadIdx.x] : 0;
    s[threadIdx.x] = v;
    __syncthreads();
    for (int d = 1; d < 512; d <<= 1) {
        int t = (threadIdx.x >= d) ? s[threadIdx.x - d] : 0;
        __syncthreads();
        s[threadIdx.x] += t;
        __syncthreads();
    }
    if (threadIdx.x < NBLK) g_partial[threadIdx.x] = s[threadIdx.x] - v;
}

__global__ void scan3_kernel() {
    int i = blockIdx.x * blockDim.x + threadIdx.x;
    if (i < SEG) g_off[i] += g_partial[i / SCAN_B];
}

// ---- fill CSR: edge src ids sorted by (dst, rel) segment ----
__global__ void fill_kernel(const int* __restrict__ src,
                            const int* __restrict__ dst,
                            const int* __restrict__ et) {
    int e = blockIdx.x * blockDim.x + threadIdx.x;
    if (e < N_EDGES) {
        int sg  = dst[e] * R + et[e];
        int pos = g_off[sg] + atomicAdd(&g_fill[sg], 1);
        g_esrc[pos] = src[e];
    }
}

// ---- fused per-layer kernel: CSR gather (mean per (node,rel)) + transform ----
// block = 256 threads handles NB nodes.
// gather: GS = 256/(NB*R) threads per (node,rel), F = DIN/GS floats each.
// transform: thread per (node, 4-output chunk): NB * DOUT/4 == 256.
template <int DIN, int DOUT, int NB, bool RELU>
__global__ void layer_kernel(const float* __restrict__ xin,
                             const float* __restrict__ W,     // [R, DIN, DOUT]
                             const float* __restrict__ root,  // [DIN, DOUT]
                             const float* __restrict__ bias,  // [DOUT]
                             float* __restrict__ hout) {
    constexpr int GS  = 256 / (NB * R);
    constexpr int F   = DIN / GS;
    constexpr int NF4 = F / 4;
    constexpr int WSZ = R * DIN * DOUT;
    static_assert(NB * R * GS == 256, "gather mapping");
    static_assert(NB * (DOUT / 4) == 256, "transform mapping");

    __shared__ float sAcc[NB][R][DIN];
    __shared__ float sW[WSZ];
    __shared__ float sRoot[DIN * DOUT];
    __shared__ float sBias[DOUT];

    for (int i = threadIdx.x; i < WSZ; i += 256)        sW[i] = W[i];
    for (int i = threadIdx.x; i < DIN * DOUT; i += 256) sRoot[i] = root[i];
    if (threadIdx.x < DOUT) sBias[threadIdx.x] = bias[threadIdx.x];

    int node0 = blockIdx.x * NB;

    // ---- gather phase ----
    {
        int g    = threadIdx.x / GS;
        int lane = threadIdx.x % GS;
        int nn   = g / R, r = g % R;
        int n    = node0 + nn;
        float4 acc[NF4];
#pragma unroll
        for (int f = 0; f < NF4; f++) acc[f] = make_float4(0.f, 0.f, 0.f, 0.f);
        if (n < N_NODES) {
            int sg  = n * R + r;
            int off = g_off[sg];
            int c   = g_cnt[sg];
            for (int j = 0; j < c; j++) {
                int s = g_esrc[off + j];
                const float4* xr = reinterpret_cast<const float4*>(xin + s * DIN + lane * F);
#pragma unroll
                for (int f = 0; f < NF4; f++) {
                    float4 v = xr[f];
                    acc[f].x += v.x; acc[f].y += v.y; acc[f].z += v.z; acc[f].w += v.w;
                }
            }
            float inv = 1.0f / fmaxf((float)c, 1.0f);
            float4* dp = reinterpret_cast<float4*>(&sAcc[nn][r][lane * F]);
#pragma unroll
            for (int f = 0; f < NF4; f++) {
                float4 v = acc[f];
                v.x *= inv; v.y *= inv; v.z *= inv; v.w *= inv;
                dp[f] = v;
            }
        }
    }
    __syncthreads();

    // ---- transform phase: 4 outputs per thread, float4 smem traffic ----
    {
        constexpr int OC = DOUT / 4;
        int nn = threadIdx.x / OC;
        int o0 = (threadIdx.x % OC) * 4;
        int n  = node0 + nn;
        if (n < N_NODES) {
            float4 sum = *reinterpret_cast<const float4*>(&sBias[o0]);
            // root (self) term
            const float4* xr = reinterpret_cast<const float4*>(xin + n * DIN);
#pragma unroll
            for (int i4 = 0; i4 < DIN / 4; i4++) {
                float4 a = xr[i4];
                float4 w0 = *reinterpret_cast<const float4*>(&sRoot[(i4 * 4 + 0) * DOUT + o0]);
                float4 w1 = *reinterpret_cast<const float4*>(&sRoot[(i4 * 4 + 1) * DOUT + o0]);
                float4 w2 = *reinterpret_cast<const float4*>(&sRoot[(i4 * 4 + 2) * DOUT + o0]);
                float4 w3 = *reinterpret_cast<const float4*>(&sRoot[(i4 * 4 + 3) * DOUT + o0]);
                sum.x += a.x * w0.x + a.y * w1.x + a.z * w2.x + a.w * w3.x;
                sum.y += a.x * w0.y + a.y * w1.y + a.z * w2.y + a.w * w3.y;
                sum.z += a.x * w0.z + a.y * w1.z + a.z * w2.z + a.w * w3.z;
                sum.w += a.x * w0.w + a.y * w1.w + a.z * w2.w + a.w * w3.w;
            }
            // relation terms
#pragma unroll
            for (int r = 0; r < R; r++) {
#pragma unroll
                for (int i4 = 0; i4 < DIN / 4; i4++) {
                    float4 a = *reinterpret_cast<const float4*>(&sAcc[nn][r][i4 * 4]);
                    const float* wb = &sW[(r * DIN + i4 * 4) * DOUT + o0];
                    float4 w0 = *reinterpret_cast<const float4*>(wb);
                    float4 w1 = *reinterpret_cast<const float4*>(wb + DOUT);
                    float4 w2 = *reinterpret_cast<const float4*>(wb + 2 * DOUT);
                    float4 w3 = *reinterpret_cast<const float4*>(wb + 3 * DOUT);
                    sum.x += a.x * w0.x + a.y * w1.x + a.z * w2.x + a.w * w3.x;
                    sum.y += a.x * w0.y + a.y * w1.y + a.z * w2.y + a.w * w3.y;
                    sum.z += a.x * w0.z + a.y * w1.z + a.z * w2.z + a.w * w3.z;
                    sum.w += a.x * w0.w + a.y * w1.w + a.z * w2.w + a.w * w3.w;
                }
            }
            if (RELU) {
                sum.x = fmaxf(sum.x, 0.f); sum.y = fmaxf(sum.y, 0.f);
                sum.z = fmaxf(sum.z, 0.f); sum.w = fmaxf(sum.w, 0.f);
            }
            *reinterpret_cast<float4*>(&hout[n * DOUT + o0]) = sum;
        }
    }
}

// ---- strip-reduced max pooling (batch is sorted) ----
__global__ void pool_kernel(const int* __restrict__ batch) {
    int grp = threadIdx.x / 64;          // 4 groups per block
    int c   = threadIdx.x % 64;
    int n0  = blockIdx.x * 256 + grp * 64;
    if (n0 >= N_NODES) return;
    int nend = min(n0 + 64, N_NODES);
    float cur = __int_as_float(0xff800000);   // -inf
    int curb  = batch[n0];
    for (int n = n0; n < nend; n++) {
        int   b = batch[n];
        float v = g_h3[n * 64 + c];
        if (b != curb) {
            atomicMax(&g_pool[curb * 64 + c], enc(cur));
            cur = __int_as_float(0xff800000);
            curb = b;
        }
        cur = fmaxf(cur, v);
    }
    atomicMax(&g_pool[curb * 64 + c], enc(cur));
}

__global__ void decode_kernel(float* __restrict__ out) {
    int i = blockIdx.x * blockDim.x + threadIdx.x;
    if (i < NG * 64) out[i] = dec(g_pool[i]);
}

extern "C" void kernel_launch(void* const* d_in, const int* in_sizes, int n_in,
                              void* d_out, int out_size) {
    const float* x     = (const float*)d_in[0];
    const int*   ei    = (const int*)d_in[1];
    const int*   src   = ei;
    const int*   dst   = ei + N_EDGES;
    const int*   et    = (const int*)d_in[2];
    const int*   batch = (const int*)d_in[3];
    const float* W1 = (const float*)d_in[4];
    const float* r1 = (const float*)d_in[5];
    const float* b1 = (const float*)d_in[6];
    const float* W2 = (const float*)d_in[7];
    const float* r2 = (const float*)d_in[8];
    const float* b2 = (const float*)d_in[9];
    const float* W3 = (const float*)d_in[10];
    const float* r3 = (const float*)d_in[11];
    const float* b3 = (const float*)d_in[12];
    float* out = (float*)d_out;

    float *h1p, *h2p, *h3p;
    cudaGetSymbolAddress((void**)&h1p, g_h1);
    cudaGetSymbolAddress((void**)&h2p, g_h2);
    cudaGetSymbolAddress((void**)&h3p, g_h3);

    const int T = 256;

    // CSR build (once; shared by all 3 layers)
    init_kernel<<<(SEG + T - 1) / T, T>>>();
    count_kernel<<<(N_EDGES + T - 1) / T, T>>>(dst, et);
    scan1_kernel<<<NBLK, SCAN_B>>>();
    scan2_kernel<<<1, 512>>>();
    scan3_kernel<<<(SEG + T - 1) / T, T>>>();
    fill_kernel<<<(N_EDGES + T - 1) / T, T>>>(src, dst, et);

    // fused layers
    layer_kernel<16, 16, 64, true ><<<(N_NODES + 63) / 64, T>>>(x,   W1, r1, b1, h1p);
    layer_kernel<16, 32, 32, true ><<<(N_NODES + 31) / 32, T>>>(h1p, W2, r2, b2, h2p);
    layer_kernel<32, 64, 16, false><<<(N_NODES + 15) / 16, T>>>(h2p, W3, r3, b3, h3p);

    // pooling
    pool_kernel<<<(N_NODES + 255) / 256, T>>>(batch);
    decode_kernel<<<(NG * 64 + T - 1) / T, T>>>(out);
}